// round 1
// baseline (speedup 1.0000x reference)
#include <cuda_runtime.h>
#include <math.h>

#define Bn 16384
#define Dn 512
#define Kn 16384
#define Hn 256
#define Zn 128
#define ESTR 132   // smem row stride (floats) for d-major tiles

// ---------------- scratch (static device globals; no allocation) ----------------
__device__ float g_enc[Bn * Zn];   // encoded [B, Z]
__device__ float g_c2h[Kn];        // 0.5 * ||c_k||^2
__device__ int   g_idx[Bn];        // argmin indices
__device__ float g_err[Bn];        // reconstruction error per row
__device__ float g_sum;            // sum of errors

// ---------------- encoder: X@W1+b1 -> LN -> GELU -> @W2+b2 ----------------
// One block = 32 rows. smem: Xs[32][512] + Hs[32][256] = 96KB dynamic.
__global__ void encoder_kernel(const float* __restrict__ X,
                               const float* __restrict__ W1, const float* __restrict__ b1,
                               const float* __restrict__ g1, const float* __restrict__ be1,
                               const float* __restrict__ W2, const float* __restrict__ b2)
{
    extern __shared__ float sm[];
    float* Xs = sm;                  // 32*512
    float* Hs = sm + 32 * Dn;        // 32*256
    const int tid = threadIdx.x;
    const int row0 = blockIdx.x * 32;

    // load 32 rows of features (coalesced float4)
    {
        const float4* Xg = (const float4*)(X + (size_t)row0 * Dn);
        float4* Xs4 = (float4*)Xs;
        for (int i = tid; i < 32 * Dn / 4; i += 256) Xs4[i] = Xg[i];
    }
    __syncthreads();

    // GEMM1: thread owns column `tid` for all 32 rows
    const float4* Xs4 = (const float4*)Xs;
    float acc[32];
#pragma unroll
    for (int r = 0; r < 32; ++r) acc[r] = 0.f;
    const int col = tid;
    for (int d = 0; d < Dn; d += 4) {
        float w0 = W1[(d + 0) * Hn + col];
        float w1 = W1[(d + 1) * Hn + col];
        float w2 = W1[(d + 2) * Hn + col];
        float w3 = W1[(d + 3) * Hn + col];
#pragma unroll
        for (int r = 0; r < 32; ++r) {
            float4 x = Xs4[(r * Dn + d) >> 2];   // broadcast LDS.128
            acc[r] = fmaf(x.x, w0, acc[r]);
            acc[r] = fmaf(x.y, w1, acc[r]);
            acc[r] = fmaf(x.z, w2, acc[r]);
            acc[r] = fmaf(x.w, w3, acc[r]);
        }
    }
    {
        float bb = b1[col];
#pragma unroll
        for (int r = 0; r < 32; ++r) Hs[r * Hn + col] = acc[r] + bb;
    }
    __syncthreads();

    // LayerNorm + exact GELU (warp handles 4 rows)
    {
        const int warp = tid >> 5, lane = tid & 31;
        for (int rr = 0; rr < 4; ++rr) {
            int r = warp + rr * 8;
            float s = 0.f, s2 = 0.f;
#pragma unroll
            for (int j = 0; j < 8; ++j) {
                float v = Hs[r * Hn + lane + j * 32];
                s += v; s2 += v * v;
            }
#pragma unroll
            for (int o = 16; o > 0; o >>= 1) {
                s  += __shfl_xor_sync(0xffffffff, s,  o);
                s2 += __shfl_xor_sync(0xffffffff, s2, o);
            }
            float mu  = s * (1.f / Hn);
            float var = s2 * (1.f / Hn) - mu * mu;
            float inv = rsqrtf(var + 1e-5f);
#pragma unroll
            for (int j = 0; j < 8; ++j) {
                int c = lane + j * 32;
                float v = (Hs[r * Hn + c] - mu) * inv * g1[c] + be1[c];
                Hs[r * Hn + c] = 0.5f * v * (1.f + erff(v * 0.70710678118654752f));
            }
        }
    }
    __syncthreads();

    // GEMM2: encoded[32][128]; thread -> (col = tid&127, rows rbase..rbase+15)
    {
        const float4* Hs4 = (const float4*)Hs;
        const int c2 = tid & 127;
        const int rbase = (tid >> 7) * 16;
        float a2[16];
#pragma unroll
        for (int r = 0; r < 16; ++r) a2[r] = 0.f;
        for (int d = 0; d < Hn; d += 4) {
            float w0 = W2[(d + 0) * Zn + c2];
            float w1 = W2[(d + 1) * Zn + c2];
            float w2 = W2[(d + 2) * Zn + c2];
            float w3 = W2[(d + 3) * Zn + c2];
#pragma unroll
            for (int r = 0; r < 16; ++r) {
                float4 h = Hs4[((rbase + r) * Hn + d) >> 2];
                a2[r] = fmaf(h.x, w0, a2[r]);
                a2[r] = fmaf(h.y, w1, a2[r]);
                a2[r] = fmaf(h.z, w2, a2[r]);
                a2[r] = fmaf(h.w, w3, a2[r]);
            }
        }
        float bb = b2[c2];
#pragma unroll
        for (int r = 0; r < 16; ++r)
            g_enc[(size_t)(row0 + rbase + r) * Zn + c2] = a2[r] + bb;
    }
}

// ---------------- 0.5 * ||c_k||^2, warp per code ----------------
__global__ void c2_kernel(const float* __restrict__ C)
{
    int gt = blockIdx.x * 256 + threadIdx.x;
    int code = gt >> 5;
    int lane = gt & 31;
    float4 v = ((const float4*)C)[code * 32 + lane];
    float s = v.x * v.x + v.y * v.y + v.z * v.z + v.w * v.w;
#pragma unroll
    for (int o = 16; o > 0; o >>= 1) s += __shfl_xor_sync(0xffffffff, s, o);
    if (lane == 0) g_c2h[code] = 0.5f * s;
}

// ---------------- fused distance argmin: argmax_k (e.c - 0.5||c||^2) ----------------
// block = 128 rows, loops over all K in tiles of 128 codes.
// Both tiles stored d-major in smem -> inner loop: 4x LDS.128 + 64 FFMA per d.
__global__ void dist_kernel(const float* __restrict__ C)
{
    extern __shared__ float sm[];
    float* Es  = sm;                    // [128 d][132] rows of encoded (d-major)
    float* Cs  = sm + 128 * ESTR;       // [128 d][132] codes (d-major)
    float* c2s = Cs + 128 * ESTR;       // 128

    const int tid = threadIdx.x;
    const int row0 = blockIdx.x * 128;

    // load + transpose E tile (once per block)
    for (int i = tid; i < 128 * 32; i += 256) {
        int r = i >> 5, c4 = i & 31;
        float4 v = ((const float4*)g_enc)[(size_t)(row0 + r) * 32 + c4];
        Es[(c4 * 4 + 0) * ESTR + r] = v.x;
        Es[(c4 * 4 + 1) * ESTR + r] = v.y;
        Es[(c4 * 4 + 2) * ESTR + r] = v.z;
        Es[(c4 * 4 + 3) * ESTR + r] = v.w;
    }

    const int ty = tid >> 4, tx = tid & 15;   // rows ty*8.., cols tx*8..
    float best[8]; int bidx[8];
#pragma unroll
    for (int i = 0; i < 8; ++i) { best[i] = -INFINITY; bidx[i] = 0; }

    for (int kt = 0; kt < Kn; kt += 128) {
        __syncthreads();   // protects Cs/c2s reuse; first pass also fences Es stores
        for (int i = tid; i < 128 * 32; i += 256) {
            int c = i >> 5, d4 = i & 31;
            float4 v = ((const float4*)C)[(size_t)(kt + c) * 32 + d4];
            Cs[(d4 * 4 + 0) * ESTR + c] = v.x;
            Cs[(d4 * 4 + 1) * ESTR + c] = v.y;
            Cs[(d4 * 4 + 2) * ESTR + c] = v.z;
            Cs[(d4 * 4 + 3) * ESTR + c] = v.w;
        }
        if (tid < 128) c2s[tid] = g_c2h[kt + tid];
        __syncthreads();

        float acc[8][8];
#pragma unroll
        for (int i = 0; i < 8; ++i)
#pragma unroll
            for (int j = 0; j < 8; ++j) acc[i][j] = 0.f;

#pragma unroll 4
        for (int d = 0; d < 128; ++d) {
            const float4* ep = (const float4*)(Es + d * ESTR + ty * 8);
            float4 a0 = ep[0], a1 = ep[1];
            const float4* cp = (const float4*)(Cs + d * ESTR + tx * 8);
            float4 b0 = cp[0], b1 = cp[1];
            float a[8] = {a0.x, a0.y, a0.z, a0.w, a1.x, a1.y, a1.z, a1.w};
            float b[8] = {b0.x, b0.y, b0.z, b0.w, b1.x, b1.y, b1.z, b1.w};
#pragma unroll
            for (int i = 0; i < 8; ++i)
#pragma unroll
                for (int j = 0; j < 8; ++j)
                    acc[i][j] = fmaf(a[i], b[j], acc[i][j]);
        }

        // update running argmax (ascending code order -> strict '>' keeps first index)
#pragma unroll
        for (int j = 0; j < 8; ++j) {
            int code = kt + tx * 8 + j;
            float ch = c2s[tx * 8 + j];
#pragma unroll
            for (int i = 0; i < 8; ++i) {
                float v = acc[i][j] - ch;
                if (v > best[i]) { best[i] = v; bidx[i] = code; }
            }
        }
    }
    __syncthreads();

    // cross-thread (tx) reduction per row, tie -> lower index
    float* redv = Cs;
    int*   redi = (int*)(Cs + 128 * 16);
#pragma unroll
    for (int i = 0; i < 8; ++i) {
        int r = ty * 8 + i;
        redv[r * 16 + tx] = best[i];
        redi[r * 16 + tx] = bidx[i];
    }
    __syncthreads();
    if (tid < 128) {
        float bv = redv[tid * 16]; int bi = redi[tid * 16];
        for (int t = 1; t < 16; ++t) {
            float v = redv[tid * 16 + t]; int ix = redi[tid * 16 + t];
            if (v > bv || (v == bv && ix < bi)) { bv = v; bi = ix; }
        }
        g_idx[row0 + tid] = bi;
    }
}

// ---------------- decoder: gather -> @W3+b3 -> LN -> GELU -> @W4+b4 -> err ----------------
__global__ void decoder_kernel(const float* __restrict__ C,
                               const float* __restrict__ W3, const float* __restrict__ b3,
                               const float* __restrict__ g2, const float* __restrict__ be2,
                               const float* __restrict__ W4, const float* __restrict__ b4,
                               const float* __restrict__ X)
{
    extern __shared__ float sm[];
    float* Qs = sm;                  // 32*128
    float* Hs = sm + 32 * Zn;        // 32*256
    float* ep = Hs + 32 * Hn;        // 32*8 per-warp error partials
    const int tid = threadIdx.x;
    const int row0 = blockIdx.x * 32;

    // gather quantized rows
    for (int i = tid; i < 32 * 32; i += 256) {
        int r = i >> 5, d4 = i & 31;
        int code = g_idx[row0 + r];
        ((float4*)Qs)[r * 32 + d4] = ((const float4*)C)[(size_t)code * 32 + d4];
    }
    __syncthreads();

    // GEMM1: Q[32x128] @ W3[128x256]
    {
        const float4* Qs4 = (const float4*)Qs;
        float acc[32];
#pragma unroll
        for (int r = 0; r < 32; ++r) acc[r] = 0.f;
        const int col = tid;
        for (int d = 0; d < Zn; d += 4) {
            float w0 = W3[(d + 0) * Hn + col];
            float w1 = W3[(d + 1) * Hn + col];
            float w2 = W3[(d + 2) * Hn + col];
            float w3 = W3[(d + 3) * Hn + col];
#pragma unroll
            for (int r = 0; r < 32; ++r) {
                float4 q = Qs4[(r * Zn + d) >> 2];
                acc[r] = fmaf(q.x, w0, acc[r]);
                acc[r] = fmaf(q.y, w1, acc[r]);
                acc[r] = fmaf(q.z, w2, acc[r]);
                acc[r] = fmaf(q.w, w3, acc[r]);
            }
        }
        float bb = b3[col];
#pragma unroll
        for (int r = 0; r < 32; ++r) Hs[r * Hn + col] = acc[r] + bb;
    }
    __syncthreads();

    // LN + GELU
    {
        const int warp = tid >> 5, lane = tid & 31;
        for (int rr = 0; rr < 4; ++rr) {
            int r = warp + rr * 8;
            float s = 0.f, s2 = 0.f;
#pragma unroll
            for (int j = 0; j < 8; ++j) {
                float v = Hs[r * Hn + lane + j * 32];
                s += v; s2 += v * v;
            }
#pragma unroll
            for (int o = 16; o > 0; o >>= 1) {
                s  += __shfl_xor_sync(0xffffffff, s,  o);
                s2 += __shfl_xor_sync(0xffffffff, s2, o);
            }
            float mu  = s * (1.f / Hn);
            float var = s2 * (1.f / Hn) - mu * mu;
            float inv = rsqrtf(var + 1e-5f);
#pragma unroll
            for (int j = 0; j < 8; ++j) {
                int c = lane + j * 32;
                float v = (Hs[r * Hn + c] - mu) * inv * g2[c] + be2[c];
                Hs[r * Hn + c] = 0.5f * v * (1.f + erff(v * 0.70710678118654752f));
            }
        }
    }
    __syncthreads();

    // GEMM2: H[32x256] @ W4[256x512]; thread owns cols {tid, tid+256}
    float aA[32], aB[32];
#pragma unroll
    for (int r = 0; r < 32; ++r) { aA[r] = 0.f; aB[r] = 0.f; }
    {
        const float4* Hs4 = (const float4*)Hs;
        for (int d = 0; d < Hn; d += 4) {
            float wa0 = W4[(d + 0) * Dn + tid];
            float wa1 = W4[(d + 1) * Dn + tid];
            float wa2 = W4[(d + 2) * Dn + tid];
            float wa3 = W4[(d + 3) * Dn + tid];
            float wb0 = W4[(d + 0) * Dn + tid + 256];
            float wb1 = W4[(d + 1) * Dn + tid + 256];
            float wb2 = W4[(d + 2) * Dn + tid + 256];
            float wb3 = W4[(d + 3) * Dn + tid + 256];
#pragma unroll
            for (int r = 0; r < 32; ++r) {
                float4 h = Hs4[(r * Hn + d) >> 2];
                aA[r] = fmaf(h.x, wa0, aA[r]);
                aA[r] = fmaf(h.y, wa1, aA[r]);
                aA[r] = fmaf(h.z, wa2, aA[r]);
                aA[r] = fmaf(h.w, wa3, aA[r]);
                aB[r] = fmaf(h.x, wb0, aB[r]);
                aB[r] = fmaf(h.y, wb1, aB[r]);
                aB[r] = fmaf(h.z, wb2, aB[r]);
                aB[r] = fmaf(h.w, wb3, aB[r]);
            }
        }
    }

    // per-row reconstruction error (deterministic reduction)
    {
        const int warp = tid >> 5, lane = tid & 31;
        float b4a = b4[tid], b4b = b4[tid + 256];
        for (int r = 0; r < 32; ++r) {
            float f1 = X[(size_t)(row0 + r) * Dn + tid];
            float f2 = X[(size_t)(row0 + r) * Dn + tid + 256];
            float d1 = aA[r] + b4a - f1;
            float d2 = aB[r] + b4b - f2;
            float e = d1 * d1 + d2 * d2;
#pragma unroll
            for (int o = 16; o > 0; o >>= 1) e += __shfl_xor_sync(0xffffffff, e, o);
            if (lane == 0) ep[r * 8 + warp] = e;
        }
        __syncthreads();
        if (tid < 32) {
            float s = 0.f;
#pragma unroll
            for (int w = 0; w < 8; ++w) s += ep[tid * 8 + w];
            g_err[row0 + tid] = s * (1.f / Dn);
        }
    }
}

// ---------------- global mean (single block, deterministic) ----------------
__global__ void reduce_kernel()
{
    __shared__ float s[256];
    int tid = threadIdx.x;
    float a = 0.f;
    for (int i = tid; i < Bn; i += 256) a += g_err[i];
    s[tid] = a;
    __syncthreads();
    for (int o = 128; o > 0; o >>= 1) {
        if (tid < o) s[tid] += s[tid + o];
        __syncthreads();
    }
    if (tid == 0) g_sum = s[0];
}

// ---------------- MDL bits + output assembly ----------------
__global__ void final_kernel(float* __restrict__ out)
{
    int i = blockIdx.x * 256 + threadIdx.x;
    float scale = g_sum * (1.f / Bn) + 1e-8f;
    float err = g_err[i];
    float eb = (fabsf(err) / scale + logf(2.f * scale)) * 1.4426950408889634f;
    float tb = 14.f + eb;                 // log2(16384) = 14
    out[i]          = err;
    out[Bn + i]     = (Dn * 32.f) / tb;   // compression ratio
    out[2 * Bn + i] = tb;
    out[3 * Bn + i] = (float)g_idx[i];
}

// ---------------- launch ----------------
extern "C" void kernel_launch(void* const* d_in, const int* in_sizes, int n_in,
                              void* d_out, int out_size)
{
    const float* X   = (const float*)d_in[0];
    const float* W1  = (const float*)d_in[1];
    const float* b1  = (const float*)d_in[2];
    const float* g1  = (const float*)d_in[3];
    const float* be1 = (const float*)d_in[4];
    const float* W2  = (const float*)d_in[5];
    const float* b2  = (const float*)d_in[6];
    const float* CB  = (const float*)d_in[7];
    const float* W3  = (const float*)d_in[8];
    const float* b3  = (const float*)d_in[9];
    const float* g2  = (const float*)d_in[10];
    const float* be2 = (const float*)d_in[11];
    const float* W4  = (const float*)d_in[12];
    const float* b4  = (const float*)d_in[13];
    float* out = (float*)d_out;

    cudaFuncSetAttribute(encoder_kernel, cudaFuncAttributeMaxDynamicSharedMemorySize, 98304);
    cudaFuncSetAttribute(dist_kernel,    cudaFuncAttributeMaxDynamicSharedMemorySize, 135680);
    cudaFuncSetAttribute(decoder_kernel, cudaFuncAttributeMaxDynamicSharedMemorySize, 50176);

    encoder_kernel<<<Bn / 32, 256, 98304>>>(X, W1, b1, g1, be1, W2, b2);
    c2_kernel<<<Kn / 8, 256>>>(CB);
    dist_kernel<<<Bn / 128, 256, 135680>>>(CB);
    decoder_kernel<<<Bn / 32, 256, 50176>>>(CB, W3, b3, g2, be2, W4, b4, X);
    reduce_kernel<<<1, 256>>>();
    final_kernel<<<Bn / 256, 256>>>(out);
}